// round 2
// baseline (speedup 1.0000x reference)
#include <cuda_runtime.h>

#define SO 160                 // fine grid size
#define SV (SO*SO*SO)
#define DC 96                  // coarse grid size
#define IMH 240
#define IMW 320
#define NVIEW 3
#define NPIX (NVIEW*IMH*IMW)

// ---- device-global scratch (no cudaMalloc allowed) ----
__device__ float  g_sdf[SV];                 // fine SDF (already -1.5), 16 MB
__device__ float4 g4[SV];                    // packed yz-quad SDF, 64 MB
__device__ float  g_t[NPIX];                 // final ray parameter per pixel
__device__ double g_sum;                     // loss numerator
__device__ unsigned int g_cnt;               // count of valid pixels

__constant__ float c_off[3][3] = {{0.f,0.f,0.f},{36.f,0.f,44.f},{40.f,0.f,23.f}};

// ------------------------------------------------------------------
__global__ void k_zero() { g_sum = 0.0; g_cnt = 0u; }

// ------------------------------------------------------------------
// Trilinear upsample coarse SDF (96^3) -> fine (160^3), minus TRUNC.
__global__ void k_resize(const float* __restrict__ src) {
    int idx = blockIdx.x * blockDim.x + threadIdx.x;
    if (idx >= SV) return;
    int z = idx % SO;
    int y = (idx / SO) % SO;
    int x = idx / (SO * SO);

    const float SCL = 95.0f / 159.0f;
    float cx = x * SCL, cy = y * SCL, cz = z * SCL;
    int x0 = (int)cx, y0 = (int)cy, z0 = (int)cz;
    x0 = min(x0, DC - 1); y0 = min(y0, DC - 1); z0 = min(z0, DC - 1);
    float fx = cx - (float)x0, fy = cy - (float)y0, fz = cz - (float)z0;
    int x1 = min(x0 + 1, DC - 1), y1 = min(y0 + 1, DC - 1), z1 = min(z0 + 1, DC - 1);

    int i00 = (x0 * DC + y0) * DC;
    int i01 = (x0 * DC + y1) * DC;
    int i10 = (x1 * DC + y0) * DC;
    int i11 = (x1 * DC + y1) * DC;
    float c000 = __ldg(&src[i00 + z0]), c001 = __ldg(&src[i00 + z1]);
    float c010 = __ldg(&src[i01 + z0]), c011 = __ldg(&src[i01 + z1]);
    float c100 = __ldg(&src[i10 + z0]), c101 = __ldg(&src[i10 + z1]);
    float c110 = __ldg(&src[i11 + z0]), c111 = __ldg(&src[i11 + z1]);

    float gx = 1.f - fx, gy = 1.f - fy, gz = 1.f - fz;
    float val = c000*gx*gy*gz + c100*fx*gy*gz + c010*gx*fy*gz + c001*gx*gy*fz
              + c110*fx*fy*gz + c101*fx*gy*fz + c011*gx*fy*fz + c111*fx*fy*fz;
    g_sdf[idx] = val - 1.5f;
}

// ------------------------------------------------------------------
// Pack: g4[x][y][z] = { v(x,y,z), v(x,y,z+1), v(x,y+1,z), v(x,y+1,z+1) }
__global__ void k_pack() {
    int idx = blockIdx.x * blockDim.x + threadIdx.x;
    if (idx >= SV) return;
    int z = idx % SO;
    int y = (idx / SO) % SO;
    int zp = min(z + 1, SO - 1);
    int yo = (min(y + 1, SO - 1) - y) * SO;   // 0 or SO
    float4 q;
    q.x = g_sdf[idx];
    q.y = g_sdf[idx - z + zp];
    q.z = g_sdf[idx + yo];
    q.w = g_sdf[idx + yo - z + zp];
    g4[idx] = q;
}

// ------------------------------------------------------------------
// Trilerp of the fine SDF grid (scalar path, used by shade)
__device__ __forceinline__ float tl_sdf(float px, float py, float pz) {
    px = fminf(fmaxf(px, 0.0f), 158.999f);
    py = fminf(fmaxf(py, 0.0f), 158.999f);
    pz = fminf(fmaxf(pz, 0.0f), 158.999f);
    int x0 = (int)px, y0 = (int)py, z0 = (int)pz;
    float fx = px - (float)x0, fy = py - (float)y0, fz = pz - (float)z0;
    int x1 = min(x0 + 1, SO - 1), y1 = min(y0 + 1, SO - 1), z1 = min(z0 + 1, SO - 1);

    int i00 = (x0 * SO + y0) * SO;
    int i01 = (x0 * SO + y1) * SO;
    int i10 = (x1 * SO + y0) * SO;
    int i11 = (x1 * SO + y1) * SO;
    float c000 = __ldg(&g_sdf[i00 + z0]), c001 = __ldg(&g_sdf[i00 + z1]);
    float c010 = __ldg(&g_sdf[i01 + z0]), c011 = __ldg(&g_sdf[i01 + z1]);
    float c100 = __ldg(&g_sdf[i10 + z0]), c101 = __ldg(&g_sdf[i10 + z1]);
    float c110 = __ldg(&g_sdf[i11 + z0]), c111 = __ldg(&g_sdf[i11 + z1]);

    float gx = 1.f - fx, gy = 1.f - fy, gz = 1.f - fz;
    return c000*gx*gy*gz + c100*fx*gy*gz + c010*gx*fy*gz + c001*gx*gy*fz
         + c110*fx*fy*gz + c101*fx*gy*fz + c011*gx*fy*fz + c111*fx*fy*fz;
}

// Recompute ray (origin, dir) for view v, pixel (h, w)
__device__ __forceinline__ void ray_setup_vhw(const float* __restrict__ poses,
                                              int v, int h, int w,
                                              float& ox, float& oy, float& oz,
                                              float& dx, float& dy, float& dz) {
    const float* M = poses + v * 16;
    float u  = ((float)w - 160.0f) / 277.0f;
    float vv = ((float)h - 120.0f) / 277.0f;
    dx = M[0] * u + M[1] * vv + M[2];
    dy = M[4] * u + M[5] * vv + M[6];
    dz = M[8] * u + M[9] * vv + M[10];
    float inv = rsqrtf(dx * dx + dy * dy + dz * dz);
    dx *= inv; dy *= inv; dz *= inv;
    ox = M[3]  / 0.0301f + c_off[v][0];
    oy = M[7]  / 0.0301f + c_off[v][1];
    oz = M[11] / 0.0301f + c_off[v][2];
}

// ------------------------------------------------------------------
// Sphere trace: 64 dependent steps per ray, packed-float4 SDF fetch,
// magic-number floor (no F2I/I2F in the loop).
__global__ void __launch_bounds__(256) k_march(const float* __restrict__ poses) {
    // 16x16 pixel tile per block for 3-D gather locality
    int tx = threadIdx.x & 15;
    int ty = threadIdx.x >> 4;
    int w = blockIdx.x * 16 + tx;
    int h = blockIdx.y * 16 + ty;
    int v = blockIdx.z;

    float ox, oy, oz, dx, dy, dz;
    ray_setup_vhw(poses, v, h, w, ox, oy, oz, dx, dy, dz);

    const float MAG  = 8388608.0f;           // 2^23
    const float MAGH = 8388607.5f;           // 2^23 - 0.5
    const int   MAGI = 0x4B000000;           // bits of 2^23

    float t = 0.0f;
    #pragma unroll 1
    for (int i = 0; i < 64; i++) {
        float px = ox + t * dx;
        float py = oy + t * dy;
        float pz = oz + t * dz;
        px = fminf(fmaxf(px, 0.0f), 158.999f);
        py = fminf(fmaxf(py, 0.0f), 158.999f);
        pz = fminf(fmaxf(pz, 0.0f), 158.999f);

        // floor via magic number: p0 in [0,158], frac may be exactly 1.0 at
        // RTE ties (value still correct by lerp continuity)
        float txm = px + MAGH;  float x0f = txm - MAG;  float fx = px - x0f;
        float tym = py + MAGH;  float y0f = tym - MAG;  float fy = py - y0f;
        float tzm = pz + MAGH;  float z0f = tzm - MAG;  float fz = pz - z0f;
        int x0 = __float_as_int(txm) - MAGI;
        int y0 = __float_as_int(tym) - MAGI;
        int z0 = __float_as_int(tzm) - MAGI;

        int idx = (x0 * SO + y0) * SO + z0;
        float4 A = __ldg(&g4[idx]);               // x0 plane
        float4 B = __ldg(&g4[idx + SO * SO]);     // x0+1 plane (imm offset)

        // bilinear in (y,z) on each plane, then lerp in x
        float a0 = A.x + fz * (A.y - A.x);
        float a1 = A.z + fz * (A.w - A.z);
        float ea = a0 + fy * (a1 - a0);
        float b0 = B.x + fz * (B.y - B.x);
        float b1 = B.z + fz * (B.w - B.z);
        float eb = b0 + fy * (b1 - b0);
        float s  = ea + fx * (eb - ea);

        t += fmaxf(s, 0.25f) * 2.0f;
    }
    g_t[(v * IMH + h) * IMW + w] = t;
}

// ------------------------------------------------------------------
// Final shading + masked weighted-L1 reduction.
__global__ void __launch_bounds__(128) k_shade(const float* __restrict__ poses,
                                               const float* __restrict__ rgb,
                                               const float* __restrict__ sem,
                                               const float* __restrict__ views) {
    int idx = blockIdx.x * blockDim.x + threadIdx.x;
    float contrib = 0.0f;
    int cval = 0;

    if (idx < NPIX) {
        int w = idx % IMW;
        int h = (idx / IMW) % IMH;
        int v = idx / (IMW * IMH);
        float ox, oy, oz, dx, dy, dz;
        ray_setup_vhw(poses, v, h, w, ox, oy, oz, dx, dy, dz);
        float t = g_t[idx];
        float px = ox + t * dx;
        float py = oy + t * dy;
        float pz = oz + t * dz;
        float s = tl_sdf(px, py, pz);
        bool inside = (px >= 0.f) && (px <= 159.f) &&
                      (py >= 0.f) && (py <= 159.f) &&
                      (pz >= 0.f) && (pz <= 159.f);
        if (inside && fabsf(s) < 1.0f) {
            // fine-grid cell of pos (reference clip)
            float cpx = fminf(fmaxf(px, 0.0f), 158.999f);
            float cpy = fminf(fmaxf(py, 0.0f), 158.999f);
            float cpz = fminf(fmaxf(pz, 0.0f), 158.999f);
            int X0 = (int)cpx, Y0 = (int)cpy, Z0 = (int)cpz;
            float FXf = cpx - (float)X0, FYf = cpy - (float)Y0, FZf = cpz - (float)Z0;
            int Xc[2] = {X0, min(X0 + 1, SO - 1)};
            int Yc[2] = {Y0, min(Y0 + 1, SO - 1)};
            int Zc[2] = {Z0, min(Z0 + 1, SO - 1)};
            float WX[2] = {1.f - FXf, FXf};
            float WY[2] = {1.f - FYf, FYf};
            float WZ[2] = {1.f - FZf, FZf};

            // per-axis coarse mapping for the 2 fine corners on each axis
            const float SCL = 95.0f / 159.0f;
            int   GX0[2], GX1[2], SX[2]; float GFX[2];
            int   GY0[2], GY1[2], SY[2]; float GFY[2];
            int   GZ0[2], GZ1[2], SZ[2]; float GFZ[2];
            #pragma unroll
            for (int a = 0; a < 2; a++) {
                float cc;
                cc = (float)Xc[a] * SCL;
                GX0[a] = min((int)cc, DC - 1); GFX[a] = cc - (float)GX0[a]; GX1[a] = min(GX0[a] + 1, DC - 1);
                SX[a] = min((int)((float)Xc[a] * 0.6f), DC - 1);
                cc = (float)Yc[a] * SCL;
                GY0[a] = min((int)cc, DC - 1); GFY[a] = cc - (float)GY0[a]; GY1[a] = min(GY0[a] + 1, DC - 1);
                SY[a] = min((int)((float)Yc[a] * 0.6f), DC - 1);
                cc = (float)Zc[a] * SCL;
                GZ0[a] = min((int)cc, DC - 1); GFZ[a] = cc - (float)GZ0[a]; GZ1[a] = min(GZ0[a] + 1, DC - 1);
                SZ[a] = min((int)((float)Zc[a] * 0.6f), DC - 1);
            }

            float rr = 0.f, gg = 0.f, bb = 0.f, ws = 0.f;
            const int DD = DC * DC * DC;
            #pragma unroll
            for (int a = 0; a < 2; a++) {
                #pragma unroll
                for (int b = 0; b < 2; b++) {
                    #pragma unroll
                    for (int c = 0; c < 2; c++) {
                        float wgt = WX[a] * WY[b] * WZ[c];
                        float fx = GFX[a], fy = GFY[b], fz = GFZ[c];
                        float gx = 1.f - fx, gy = 1.f - fy, gz = 1.f - fz;
                        float w000 = gx*gy*gz, w100 = fx*gy*gz, w010 = gx*fy*gz, w001 = gx*gy*fz;
                        float w110 = fx*fy*gz, w101 = fx*gy*fz, w011 = gx*fy*fz, w111 = fx*fy*fz;
                        int i00 = (GX0[a] * DC + GY0[b]) * DC;
                        int i01 = (GX0[a] * DC + GY1[b]) * DC;
                        int i10 = (GX1[a] * DC + GY0[b]) * DC;
                        int i11 = (GX1[a] * DC + GY1[b]) * DC;
                        int z0 = GZ0[c], z1 = GZ1[c];
                        #pragma unroll
                        for (int ch = 0; ch < 3; ch++) {
                            const float* base = rgb + ch * DD;
                            float val = __ldg(&base[i00 + z0]) * w000
                                      + __ldg(&base[i10 + z0]) * w100
                                      + __ldg(&base[i01 + z0]) * w010
                                      + __ldg(&base[i00 + z1]) * w001
                                      + __ldg(&base[i11 + z0]) * w110
                                      + __ldg(&base[i10 + z1]) * w101
                                      + __ldg(&base[i01 + z1]) * w011
                                      + __ldg(&base[i11 + z1]) * w111;
                            if (ch == 0) rr += wgt * val;
                            else if (ch == 1) gg += wgt * val;
                            else bb += wgt * val;
                        }
                        ws += wgt * __ldg(&sem[(SX[a] * DC + SY[b]) * DC + SZ[c]]);
                    }
                }
            }

            const float* vp = views + ((size_t)(v * IMH + h) * IMW + w) * 3;
            float l = fabsf(rr - vp[0]) + fabsf(gg - vp[1]) + fabsf(bb - vp[2]);
            contrib = ws * l;
            cval = 1;
        }
    }

    // warp reduce
    #pragma unroll
    for (int o = 16; o > 0; o >>= 1) {
        contrib += __shfl_down_sync(0xFFFFFFFFu, contrib, o);
        cval    += __shfl_down_sync(0xFFFFFFFFu, cval, o);
    }
    __shared__ float ssum[4];
    __shared__ int scnt[4];
    int lane = threadIdx.x & 31;
    int wid = threadIdx.x >> 5;
    if (lane == 0) { ssum[wid] = contrib; scnt[wid] = cval; }
    __syncthreads();
    if (wid == 0) {
        float bs = (lane < 4) ? ssum[lane] : 0.f;
        int bc = (lane < 4) ? scnt[lane] : 0;
        #pragma unroll
        for (int o = 2; o > 0; o >>= 1) {
            bs += __shfl_down_sync(0xFFFFFFFFu, bs, o);
            bc += __shfl_down_sync(0xFFFFFFFFu, bc, o);
        }
        if (lane == 0) {
            if (bs != 0.f) atomicAdd(&g_sum, (double)bs);
            if (bc) atomicAdd(&g_cnt, (unsigned int)bc);
        }
    }
}

// ------------------------------------------------------------------
__global__ void k_final(float* __restrict__ out) {
    double num_valid = 3.0 * (double)g_cnt;
    double denom = num_valid > 1.0 ? num_valid : 1.0;
    out[0] = (float)(8.0 * g_sum / denom);
}

// ------------------------------------------------------------------
extern "C" void kernel_launch(void* const* d_in, const int* in_sizes, int n_in,
                              void* d_out, int out_size) {
    const float* sdf   = (const float*)d_in[0];
    const float* rgb   = (const float*)d_in[1];
    const float* sem   = (const float*)d_in[2];
    const float* poses = (const float*)d_in[3];
    const float* views = (const float*)d_in[4];

    k_zero<<<1, 1>>>();
    k_resize<<<(SV + 255) / 256, 256>>>(sdf);
    k_pack<<<(SV + 255) / 256, 256>>>();
    dim3 mg(IMW / 16, IMH / 16, NVIEW);
    k_march<<<mg, 256>>>(poses);
    k_shade<<<(NPIX + 127) / 128, 128>>>(poses, rgb, sem, views);
    k_final<<<1, 1>>>((float*)d_out);
}